// round 1
// baseline (speedup 1.0000x reference)
#include <cuda_runtime.h>

#define Bc 4
#define Tt 1024
#define Dd 512
#define Cc 8
#define Hh 8
#define HD 64

// ---------------- scratch (device globals: no allocation allowed) ----------
__device__ float g_Q[Bc * Hh * Tt * HD];     // 8 MB
__device__ float g_K[Bc * Hh * Tt * HD];     // 8 MB
__device__ float g_V[Bc * Hh * Tt * HD];     // 8 MB
__device__ float g_ctx[Bc * Tt * Dd];        // 8 MB
__device__ int   g_assign[Bc * Tt];
__device__ int   g_counts[Bc * Cc];
__device__ int   g_list[Bc * Tt];            // tokens grouped by cluster per batch

// ---------------- 0) zero the counts -------------------------------------
__global__ void k_zero() {
    int t = threadIdx.x;
    if (t < Bc * Cc) g_counts[t] = 0;
}

// ---------------- 1) cluster argmax (one warp per token) ------------------
__global__ void k_assign(const float* __restrict__ X,
                         const float* __restrict__ Wc,
                         const float* __restrict__ bc) {
    int gw   = (blockIdx.x * blockDim.x + threadIdx.x) >> 5;   // token row
    int lane = threadIdx.x & 31;
    if (gw >= Bc * Tt) return;
    const float* x = X + (size_t)gw * Dd;
    double best = -1e300; int bi = 0;
#pragma unroll
    for (int c = 0; c < Cc; c++) {
        const float* w = Wc + c * Dd;
        double p = 0.0;
        for (int d = lane; d < Dd; d += 32) p += (double)x[d] * (double)w[d];
#pragma unroll
        for (int o = 16; o; o >>= 1) p += __shfl_xor_sync(0xffffffffu, p, o);
        double s = p + (double)bc[c];
        if (s > best) { best = s; bi = c; }   // strict > == first-max (jnp.argmax)
    }
    if (lane == 0) {
        g_assign[gw] = bi;
        atomicAdd(&g_counts[(gw >> 10) * Cc + bi], 1);
    }
}

// ---------------- 2) deterministic gather of tokens per (b, cluster) ------
__global__ void k_scatter() {
    int gt = blockIdx.x * blockDim.x + threadIdx.x;
    if (gt >= Bc * Tt) return;
    int b = gt >> 10;
    int t = gt & 1023;
    int c = g_assign[gt];
    int off = 0;
#pragma unroll
    for (int i = 0; i < Cc; i++) off += (i < c) ? g_counts[b * Cc + i] : 0;
    int pos = 0;                                   // rank of t within its cluster
    const int* ap = g_assign + b * Tt;
    for (int tp = 0; tp < t; tp++) pos += (ap[tp] == c);
    g_list[b * Tt + off + pos] = t;
}

// ---------------- 3/5) fp32 NT GEMM: C[M,N] = A[M,K] * B[N,K]^T + bias ----
// 128x128 tile, 8x8 per thread, 256 threads, BK=16.
// MODE 0: A=X, B=Win -> scatter to g_Q/g_K/g_V ([B,H,T,64] each)
// MODE 1: A=g_ctx, B=Wout -> Co row-major [M,512]
template <int MODE>
__global__ void __launch_bounds__(256) k_gemm(const float* __restrict__ A_in,
                                              const float* __restrict__ Bm,
                                              const float* __restrict__ bias,
                                              float* __restrict__ Co,
                                              int Ksz) {
    __shared__ float As[16][132];
    __shared__ float Bs[16][132];
    const float* A = (MODE == 1) ? g_ctx : A_in;
    const int bm = blockIdx.y << 7, bn = blockIdx.x << 7;
    const int tid = threadIdx.x;
    const int tx = tid & 15, ty = tid >> 4;
    float acc[8][8];
#pragma unroll
    for (int i = 0; i < 8; i++)
#pragma unroll
        for (int j = 0; j < 8; j++) acc[i][j] = 0.f;

    for (int k0 = 0; k0 < Ksz; k0 += 16) {
#pragma unroll
        for (int r = 0; r < 2; r++) {
            int f = tid + (r << 8);              // 0..511
            int row = f >> 2, c4 = (f & 3) << 2;
            float4 va = *(const float4*)(A  + (size_t)(bm + row) * Ksz + k0 + c4);
            As[c4 + 0][row] = va.x; As[c4 + 1][row] = va.y;
            As[c4 + 2][row] = va.z; As[c4 + 3][row] = va.w;
            float4 vb = *(const float4*)(Bm + (size_t)(bn + row) * Ksz + k0 + c4);
            Bs[c4 + 0][row] = vb.x; Bs[c4 + 1][row] = vb.y;
            Bs[c4 + 2][row] = vb.z; Bs[c4 + 3][row] = vb.w;
        }
        __syncthreads();
#pragma unroll
        for (int kk = 0; kk < 16; kk++) {
            float a[8], b[8];
            *(float4*)&a[0] = *(const float4*)&As[kk][ty << 3];
            *(float4*)&a[4] = *(const float4*)&As[kk][(ty << 3) + 4];
            *(float4*)&b[0] = *(const float4*)&Bs[kk][tx << 3];
            *(float4*)&b[4] = *(const float4*)&Bs[kk][(tx << 3) + 4];
#pragma unroll
            for (int i = 0; i < 8; i++)
#pragma unroll
                for (int j = 0; j < 8; j++) acc[i][j] += a[i] * b[j];
        }
        __syncthreads();
    }

    if (MODE == 0) {
#pragma unroll
        for (int i = 0; i < 8; i++) {
            int m = bm + (ty << 3) + i;
            int b_ = m >> 10, t = m & 1023;
#pragma unroll
            for (int j = 0; j < 8; j++) {
                int n = bn + (tx << 3) + j;
                float v = acc[i][j] + bias[n];
                int part = n >> 9, nn = n & 511;
                int h = nn >> 6, d = nn & 63;
                float* dst = (part == 0) ? g_Q : (part == 1 ? g_K : g_V);
                dst[(((size_t)(b_ * Hh + h) * Tt + t) << 6) + d] = v;
            }
        }
    } else {
#pragma unroll
        for (int i = 0; i < 8; i++) {
            int m = bm + (ty << 3) + i;
#pragma unroll
            for (int j = 0; j < 8; j += 4) {
                int n = bn + (tx << 3) + j;
                float4 v;
                v.x = acc[i][j + 0] + bias[n + 0];
                v.y = acc[i][j + 1] + bias[n + 1];
                v.z = acc[i][j + 2] + bias[n + 2];
                v.w = acc[i][j + 3] + bias[n + 3];
                *(float4*)(Co + (size_t)m * 512 + n) = v;
            }
        }
    }
}

// ---------------- 4) cluster-gathered flash attention ---------------------
// block = (b, cluster, head, q-tile of 64). Keys: only cluster tokens, plus the
// (T - n) out-of-cluster zero-keys folded into the denominator analytically.
__global__ void __launch_bounds__(256) k_attn() {
    __shared__ float Qs[64 * 65];
    __shared__ float Ks[32 * 65];
    __shared__ float Vs[32 * 65];
    __shared__ float Ss[64 * 33];
    __shared__ float ms[64], ls[64], rs[64];
    __shared__ int qtk[64], ktk[32];

    int bid = blockIdx.x;
    int qt = bid & 15;
    int h  = (bid >> 4) & 7;
    int c  = (bid >> 7) & 7;
    int b  = bid >> 10;
    int n = g_counts[b * Cc + c];
    if (qt * 64 >= n) return;
    int base = 0;
#pragma unroll
    for (int i = 0; i < Cc; i++) base += (i < c) ? g_counts[b * Cc + i] : 0;

    int tid = threadIdx.x;
    int tx = tid & 15, ty = tid >> 4;

    if (tid < 64) {
        int qi = qt * 64 + tid;
        qtk[tid] = (qi < n) ? g_list[b * Tt + base + qi] : -1;
        ms[tid] = -1e30f; ls[tid] = 0.f;
    }
    __syncthreads();

    const float* Qb = g_Q + ((size_t)(b * Hh + h) << 16);
    const float* Kb = g_K + ((size_t)(b * Hh + h) << 16);
    const float* Vb = g_V + ((size_t)(b * Hh + h) << 16);

    // load Q tile [64 x 64]
#pragma unroll
    for (int r = 0; r < 4; r++) {
        int f = tid + (r << 8);
        int row = f >> 4, d4 = (f & 15) << 2;
        int tok = qtk[row];
        float4 v = (tok >= 0) ? *(const float4*)(Qb + ((size_t)tok << 6) + d4)
                              : make_float4(0.f, 0.f, 0.f, 0.f);
        float* q = Qs + row * 65 + d4;
        q[0] = v.x; q[1] = v.y; q[2] = v.z; q[3] = v.w;
    }

    float accO[4][4];
#pragma unroll
    for (int i = 0; i < 4; i++)
#pragma unroll
        for (int j = 0; j < 4; j++) accO[i][j] = 0.f;

    int nkt = (n + 31) >> 5;
    for (int kt = 0; kt < nkt; kt++) {
        __syncthreads();   // Q tile ready (iter 0); prior PV done; safe to reuse bufs
        if (tid < 32) {
            int ki = (kt << 5) + tid;
            ktk[tid] = (ki < n) ? g_list[b * Tt + base + ki] : -1;
        }
        __syncthreads();
        // load K/V tile [32 x 64]
#pragma unroll
        for (int r = 0; r < 2; r++) {
            int f = tid + (r << 8);
            int row = f >> 4, d4 = (f & 15) << 2;
            int tok = ktk[row];
            float4 kv = (tok >= 0) ? *(const float4*)(Kb + ((size_t)tok << 6) + d4)
                                   : make_float4(0.f, 0.f, 0.f, 0.f);
            float* kp = Ks + row * 65 + d4;
            kp[0] = kv.x; kp[1] = kv.y; kp[2] = kv.z; kp[3] = kv.w;
            float4 vv = (tok >= 0) ? *(const float4*)(Vb + ((size_t)tok << 6) + d4)
                                   : make_float4(0.f, 0.f, 0.f, 0.f);
            float* vp = Vs + row * 65 + d4;
            vp[0] = vv.x; vp[1] = vv.y; vp[2] = vv.z; vp[3] = vv.w;
        }
        __syncthreads();
        // S = Q K^T   (64 x 32), thread tile 4x2
        float accS[4][2];
#pragma unroll
        for (int i = 0; i < 4; i++) { accS[i][0] = 0.f; accS[i][1] = 0.f; }
#pragma unroll 8
        for (int kk = 0; kk < 64; kk++) {
            float a[4], bq[2];
#pragma unroll
            for (int i = 0; i < 4; i++) a[i] = Qs[((ty << 2) + i) * 65 + kk];
#pragma unroll
            for (int j = 0; j < 2; j++) bq[j] = Ks[((tx << 1) + j) * 65 + kk];
#pragma unroll
            for (int i = 0; i < 4; i++)
#pragma unroll
                for (int j = 0; j < 2; j++) accS[i][j] += a[i] * bq[j];
        }
        int krem = n - (kt << 5);     // valid key count in this tile
#pragma unroll
        for (int i = 0; i < 4; i++)
#pragma unroll
            for (int j = 0; j < 2; j++) {
                int col = (tx << 1) + j;
                Ss[((ty << 2) + i) * 33 + col] =
                    (col < krem) ? accS[i][j] * 0.125f : -1e30f;
            }
        __syncthreads();
        // online softmax per row (thread per row)
        if (tid < 64) {
            float mold = ms[tid];
            float mx = mold;
            float* srow = Ss + tid * 33;
#pragma unroll 8
            for (int k2 = 0; k2 < 32; k2++) mx = fmaxf(mx, srow[k2]);
            float sc = __expf(mold - mx);
            float lsum = ls[tid] * sc;
#pragma unroll 8
            for (int k2 = 0; k2 < 32; k2++) {
                float p = __expf(srow[k2] - mx);
                srow[k2] = p;
                lsum += p;
            }
            ms[tid] = mx; ls[tid] = lsum; rs[tid] = sc;
        }
        __syncthreads();
        // rescale + PV   (O[64x64], thread tile 4x4, kk over 32 keys)
#pragma unroll
        for (int i = 0; i < 4; i++) {
            float f = rs[(ty << 2) + i];
#pragma unroll
            for (int j = 0; j < 4; j++) accO[i][j] *= f;
        }
#pragma unroll 8
        for (int kk = 0; kk < 32; kk++) {
            float p[4], vv[4];
#pragma unroll
            for (int i = 0; i < 4; i++) p[i] = Ss[((ty << 2) + i) * 33 + kk];
#pragma unroll
            for (int j = 0; j < 4; j++) vv[j] = Vs[kk * 65 + (tx << 2) + j];
#pragma unroll
            for (int i = 0; i < 4; i++)
#pragma unroll
                for (int j = 0; j < 4; j++) accO[i][j] += p[i] * vv[j];
        }
    }
    __syncthreads();
    // fold (T - n) zero-score out-of-cluster keys into the denominator
    if (tid < 64) {
        float m = ms[tid];
        float M = fmaxf(m, 0.f);
        float denom = ls[tid] * __expf(m - M) + (float)(Tt - n) * __expf(-M);
        rs[tid] = __expf(m - M) / denom;
    }
    __syncthreads();
#pragma unroll
    for (int i = 0; i < 4; i++) {
        int r = (ty << 2) + i;
        int tok = qtk[r];
        if (tok < 0) continue;
        float f = rs[r];
        float4 o;
        o.x = accO[i][0] * f; o.y = accO[i][1] * f;
        o.z = accO[i][2] * f; o.w = accO[i][3] * f;
        *(float4*)(g_ctx + (size_t)(b * Tt + tok) * Dd + (h << 6) + (tx << 2)) = o;
    }
}

// ---------------- launch ---------------------------------------------------
extern "C" void kernel_launch(void* const* d_in, const int* in_sizes, int n_in,
                              void* d_out, int out_size) {
    const float* X    = (const float*)d_in[0];
    const float* Wc   = (const float*)d_in[1];
    const float* bc   = (const float*)d_in[2];
    const float* Win  = (const float*)d_in[3];
    const float* bin  = (const float*)d_in[4];
    const float* Wout = (const float*)d_in[5];
    const float* bout = (const float*)d_in[6];
    float* out = (float*)d_out;

    k_zero<<<1, 64>>>();
    k_assign<<<(Bc * Tt) / 8, 256>>>(X, Wc, bc);
    k_scatter<<<(Bc * Tt) / 256, 256>>>();
    k_gemm<0><<<dim3(12, 32), 256>>>(X, Win, bin, nullptr, Dd);       // QKV
    k_attn<<<Bc * Cc * Hh * 16, 256>>>();
    k_gemm<1><<<dim3(4, 32), 256>>>(nullptr, Wout, bout, out, Dd);    // out proj
}

// round 3
// speedup vs baseline: 1.4556x; 1.4556x over previous
#include <cuda_runtime.h>
#include <cuda_bf16.h>
#include <cstdint>

#define Bc 4
#define Tt 1024
#define Dd 512
#define Cc 8
#define Hh 8

// ---------------- scratch (device globals: no allocation allowed) ----------
__device__ float g_Q[Bc * Hh * Tt * 64];
__device__ float g_K[Bc * Hh * Tt * 64];
__device__ float g_V[Bc * Hh * Tt * 64];
__device__ float g_ctx[Bc * Tt * Dd];
__device__ int   g_assign[Bc * Tt];
__device__ int   g_counts[Bc * Cc];
__device__ int   g_list[Bc * Tt];
// bf16 split buffers
__device__ __nv_bfloat16 g_Xhi[Bc * Tt * Dd],   g_Xlo[Bc * Tt * Dd];
__device__ __nv_bfloat16 g_Winhi[3 * Dd * Dd],  g_Winlo[3 * Dd * Dd];
__device__ __nv_bfloat16 g_Wouthi[Dd * Dd],     g_Woutlo[Dd * Dd];
__device__ __nv_bfloat16 g_Chi[Bc * Tt * Dd],   g_Clo[Bc * Tt * Dd];

static __device__ __forceinline__ uint32_t s2u(const void* p) {
    uint32_t a;
    asm("{ .reg .u64 t; cvta.to.shared.u64 t, %1; cvt.u32.u64 %0, t; }" : "=r"(a) : "l"(p));
    return a;
}
#define LDSM4(r0, r1, r2, r3, addr) \
    asm volatile("ldmatrix.sync.aligned.m8n8.x4.shared.b16 {%0,%1,%2,%3}, [%4];" \
                 : "=r"(r0), "=r"(r1), "=r"(r2), "=r"(r3) : "r"(addr))
#define MMA16816(d, a, b) \
    asm volatile("mma.sync.aligned.m16n8k16.row.col.f32.bf16.bf16.f32 " \
                 "{%0,%1,%2,%3}, {%4,%5,%6,%7}, {%8,%9}, {%0,%1,%2,%3};" \
                 : "+f"((d)[0]), "+f"((d)[1]), "+f"((d)[2]), "+f"((d)[3]) \
                 : "r"((a)[0]), "r"((a)[1]), "r"((a)[2]), "r"((a)[3]), \
                   "r"((b)[0]), "r"((b)[1]))

// ---------------- 1) cluster argmax (one warp per token, fp64 exact) ------
__global__ void k_assign(const float* __restrict__ X,
                         const float* __restrict__ Wc,
                         const float* __restrict__ bc) {
    int gw   = (blockIdx.x * blockDim.x + threadIdx.x) >> 5;
    int lane = threadIdx.x & 31;
    if (gw >= Bc * Tt) return;
    const float* x = X + (size_t)gw * Dd;
    double best = -1e300; int bi = 0;
#pragma unroll
    for (int c = 0; c < Cc; c++) {
        const float* w = Wc + c * Dd;
        double p = 0.0;
        for (int d = lane; d < Dd; d += 32) p += (double)x[d] * (double)w[d];
#pragma unroll
        for (int o = 16; o; o >>= 1) p += __shfl_xor_sync(0xffffffffu, p, o);
        double s = p + (double)bc[c];
        if (s > best) { best = s; bi = c; }
    }
    if (lane == 0) g_assign[gw] = bi;
}

// ---------------- 2) stable per-cluster rank via ballots (1 block/batch) --
__global__ void __launch_bounds__(1024) k_rank() {
    __shared__ int warp_hist[32][8];
    __shared__ int tot[8];
    int b = blockIdx.x, t = threadIdx.x;
    int c = g_assign[b * Tt + t];
    int lane = t & 31, w = t >> 5;
    int rank_in_warp = 0;
#pragma unroll
    for (int cc = 0; cc < 8; cc++) {
        unsigned m = __ballot_sync(0xffffffffu, c == cc);
        if (cc == c) rank_in_warp = __popc(m & ((1u << lane) - 1u));
        if (lane == 0) warp_hist[w][cc] = __popc(m);
    }
    __syncthreads();
    if (t < 8) {
        int s = 0;
        for (int ww = 0; ww < 32; ww++) s += warp_hist[ww][t];
        tot[t] = s;
        g_counts[b * Cc + t] = s;
    }
    __syncthreads();
    int before = 0;
    for (int ww = 0; ww < w; ww++) before += warp_hist[ww][c];
    int base = 0;
    for (int i = 0; i < c; i++) base += tot[i];
    g_list[b * Tt + base + before + rank_in_warp] = t;
}

// ---------------- split fp32 -> bf16 hi/lo (globals picked by SEL) --------
template <int SEL>
__global__ void k_split(const float4* __restrict__ src_in, int n4) {
    const float4* src = (SEL == 3) ? (const float4*)g_ctx : src_in;
    __nv_bfloat162* hi = (SEL == 0) ? (__nv_bfloat162*)g_Xhi
                       : (SEL == 1) ? (__nv_bfloat162*)g_Winhi
                       : (SEL == 2) ? (__nv_bfloat162*)g_Wouthi
                                    : (__nv_bfloat162*)g_Chi;
    __nv_bfloat162* lo = (SEL == 0) ? (__nv_bfloat162*)g_Xlo
                       : (SEL == 1) ? (__nv_bfloat162*)g_Winlo
                       : (SEL == 2) ? (__nv_bfloat162*)g_Woutlo
                                    : (__nv_bfloat162*)g_Clo;
    int i = blockIdx.x * blockDim.x + threadIdx.x;
    if (i >= n4) return;
    float4 v = src[i];
    __nv_bfloat16 h0 = __float2bfloat16(v.x), h1 = __float2bfloat16(v.y);
    __nv_bfloat16 h2 = __float2bfloat16(v.z), h3 = __float2bfloat16(v.w);
    hi[2 * i]     = __halves2bfloat162(h0, h1);
    hi[2 * i + 1] = __halves2bfloat162(h2, h3);
    lo[2 * i]     = __halves2bfloat162(__float2bfloat16(v.x - __bfloat162float(h0)),
                                       __float2bfloat16(v.y - __bfloat162float(h1)));
    lo[2 * i + 1] = __halves2bfloat162(__float2bfloat16(v.z - __bfloat162float(h2)),
                                       __float2bfloat16(v.w - __bfloat162float(h3)));
}

// ---------------- 3/5) HMMA bf16 split GEMM -------------------------------
// C[M,N] = A[M,512] * B[N,512]^T + bias via Ahi*Bhi + Ahi*Blo + Alo*Bhi.
// CTA 128x128, 8 warps of 64x32, mma.sync m16n8k16, K-chunk 32.
// MODE 0: A=g_Xhi/lo, B=g_Winhi/lo -> scatter g_Q/g_K/g_V ([B,H,T,64]).
// MODE 1: A=g_Chi/lo, B=g_Wouthi/lo -> Co row-major [M,512].
#define APAD 40          // row stride in bf16 (80 bytes) -> ldmatrix conflict-free
template <int MODE>
__global__ void __launch_bounds__(256) k_gemm_mma(const float* __restrict__ bias,
                                                  float* __restrict__ Co) {
    __shared__ __nv_bfloat16 sA[2][128][APAD];
    __shared__ __nv_bfloat16 sB[2][128][APAD];

    const __nv_bfloat16* Ahi = MODE ? g_Chi : g_Xhi;
    const __nv_bfloat16* Alo = MODE ? g_Clo : g_Xlo;
    const __nv_bfloat16* Bhi = MODE ? g_Wouthi : g_Winhi;
    const __nv_bfloat16* Blo = MODE ? g_Woutlo : g_Winlo;

    const int tid = threadIdx.x;
    const int lane = tid & 31, wid = tid >> 5;
    const int bm = blockIdx.y << 7, bn = blockIdx.x << 7;
    const int wm = (wid >> 2) << 6;       // warp M offset (0/64)
    const int wn = (wid & 3) << 5;        // warp N offset (0/32/64/96)

    const uint32_t sbA = s2u(&sA[0][0][0]);
    const uint32_t sbB = s2u(&sB[0][0][0]);
    const int mq = lane >> 3, ri = lane & 7;
    // ldmatrix lane address bases (bytes)
    const uint32_t aBase = sbA + (uint32_t)((wm + ((mq & 1) << 3) + ri) * (APAD * 2) + ((mq >> 1) << 4));
    const uint32_t bBase = sbB + (uint32_t)((wn + ((mq >> 1) << 3) + ri) * (APAD * 2) + ((mq & 1) << 4));
    const uint32_t HOFF = 128 * APAD * 2; // hi->lo plane offset in bytes

    float acc[4][4][4];
#pragma unroll
    for (int i = 0; i < 4; i++)
#pragma unroll
        for (int j = 0; j < 4; j++)
#pragma unroll
            for (int q = 0; q < 4; q++) acc[i][j][q] = 0.f;

    for (int kc = 0; kc < 16; kc++) {
        // ---- load 4 tiles of 128x32 bf16 ----
#pragma unroll
        for (int r = 0; r < 2; r++) {
            int f = tid + (r << 8);
            int row = f >> 2, seg = f & 3;
            size_t go = (size_t)row * 512 + kc * 32 + (seg << 3);
            *(uint4*)&sA[0][row][seg << 3] = *(const uint4*)(Ahi + (size_t)bm * 512 + go);
            *(uint4*)&sA[1][row][seg << 3] = *(const uint4*)(Alo + (size_t)bm * 512 + go);
            *(uint4*)&sB[0][row][seg << 3] = *(const uint4*)(Bhi + (size_t)bn * 512 + go);
            *(uint4*)&sB[1][row][seg << 3] = *(const uint4*)(Blo + (size_t)bn * 512 + go);
        }
        __syncthreads();
#pragma unroll
        for (int k16 = 0; k16 < 2; k16++) {
            uint32_t ah[4][4], al[4][4], bh[4][2], bl[4][2];
#pragma unroll
            for (int i = 0; i < 4; i++) {
                uint32_t ad = aBase + i * (16 * APAD * 2) + k16 * 32;
                LDSM4(ah[i][0], ah[i][1], ah[i][2], ah[i][3], ad);
                LDSM4(al[i][0], al[i][1], al[i][2], al[i][3], ad + HOFF);
            }
#pragma unroll
            for (int j2 = 0; j2 < 2; j2++) {
                uint32_t bd = bBase + j2 * (16 * APAD * 2) + k16 * 32;
                LDSM4(bh[j2 * 2][0], bh[j2 * 2][1], bh[j2 * 2 + 1][0], bh[j2 * 2 + 1][1], bd);
                LDSM4(bl[j2 * 2][0], bl[j2 * 2][1], bl[j2 * 2 + 1][0], bl[j2 * 2 + 1][1], bd + HOFF);
            }
#pragma unroll
            for (int i = 0; i < 4; i++)
#pragma unroll
                for (int j = 0; j < 4; j++) {
                    MMA16816(acc[i][j], ah[i], bh[j]);
                    MMA16816(acc[i][j], ah[i], bl[j]);
                    MMA16816(acc[i][j], al[i], bh[j]);
                }
        }
        __syncthreads();
    }

    // ---- epilogue: write float2 pairs ----
    const int g = lane >> 2, q4 = lane & 3;
#pragma unroll
    for (int i = 0; i < 4; i++)
#pragma unroll
        for (int j = 0; j < 4; j++)
#pragma unroll
            for (int p = 0; p < 2; p++) {
                int m = bm + wm + i * 16 + g + p * 8;
                int n = bn + wn + j * 8 + q4 * 2;
                float2 v;
                v.x = acc[i][j][p * 2 + 0] + bias[n + 0];
                v.y = acc[i][j][p * 2 + 1] + bias[n + 1];
                if (MODE == 0) {
                    int part = n >> 9, nn = n & 511, h = nn >> 6, d = nn & 63;
                    int b_ = m >> 10, t = m & 1023;
                    float* dst = (part == 0) ? g_Q : (part == 1 ? g_K : g_V);
                    *(float2*)(dst + (((size_t)(b_ * Hh + h) * Tt + t) << 6) + d) = v;
                } else {
                    *(float2*)(Co + (size_t)m * 512 + n) = v;
                }
            }
}

// ---------------- 4) cluster-gathered flash attention ---------------------
__global__ void __launch_bounds__(256) k_attn() {
    __shared__ float Qs[64 * 65];
    __shared__ float Ks[32 * 65];
    __shared__ float Vs[32 * 65];
    __shared__ float Ss[64 * 33];
    __shared__ float ms[64], ls[64], rs[64];
    __shared__ int qtk[64], ktk[32];

    int bid = blockIdx.x;
    int qt = bid & 15;
    int h  = (bid >> 4) & 7;
    int c  = (bid >> 7) & 7;
    int b  = bid >> 10;
    int n = g_counts[b * Cc + c];
    if (qt * 64 >= n) return;
    int base = 0;
#pragma unroll
    for (int i = 0; i < Cc; i++) base += (i < c) ? g_counts[b * Cc + i] : 0;

    int tid = threadIdx.x;
    int tx = tid & 15, ty = tid >> 4;

    if (tid < 64) {
        int qi = qt * 64 + tid;
        qtk[tid] = (qi < n) ? g_list[b * Tt + base + qi] : -1;
        ms[tid] = -1e30f; ls[tid] = 0.f;
    }
    __syncthreads();

    const float* Qb = g_Q + ((size_t)(b * Hh + h) << 16);
    const float* Kb = g_K + ((size_t)(b * Hh + h) << 16);
    const float* Vb = g_V + ((size_t)(b * Hh + h) << 16);

#pragma unroll
    for (int r = 0; r < 4; r++) {
        int f = tid + (r << 8);
        int row = f >> 4, d4 = (f & 15) << 2;
        int tok = qtk[row];
        float4 v = (tok >= 0) ? *(const float4*)(Qb + ((size_t)tok << 6) + d4)
                              : make_float4(0.f, 0.f, 0.f, 0.f);
        float* q = Qs + row * 65 + d4;
        q[0] = v.x; q[1] = v.y; q[2] = v.z; q[3] = v.w;
    }

    float accO[4][4];
#pragma unroll
    for (int i = 0; i < 4; i++)
#pragma unroll
        for (int j = 0; j < 4; j++) accO[i][j] = 0.f;

    int nkt = (n + 31) >> 5;
    for (int kt = 0; kt < nkt; kt++) {
        __syncthreads();
        if (tid < 32) {
            int ki = (kt << 5) + tid;
            ktk[tid] = (ki < n) ? g_list[b * Tt + base + ki] : -1;
        }
        __syncthreads();
#pragma unroll
        for (int r = 0; r < 2; r++) {
            int f = tid + (r << 8);
            int row = f >> 4, d4 = (f & 15) << 2;
            int tok = ktk[row];
            float4 kv = (tok >= 0) ? *(const float4*)(Kb + ((size_t)tok << 6) + d4)
                                   : make_float4(0.f, 0.f, 0.f, 0.f);
            float* kp = Ks + row * 65 + d4;
            kp[0] = kv.x; kp[1] = kv.y; kp[2] = kv.z; kp[3] = kv.w;
            float4 vv = (tok >= 0) ? *(const float4*)(Vb + ((size_t)tok << 6) + d4)
                                   : make_float4(0.f, 0.f, 0.f, 0.f);
            float* vp = Vs + row * 65 + d4;
            vp[0] = vv.x; vp[1] = vv.y; vp[2] = vv.z; vp[3] = vv.w;
        }
        __syncthreads();
        float accS[4][2];
#pragma unroll
        for (int i = 0; i < 4; i++) { accS[i][0] = 0.f; accS[i][1] = 0.f; }
#pragma unroll 8
        for (int kk = 0; kk < 64; kk++) {
            float a[4], bq[2];
#pragma unroll
            for (int i = 0; i < 4; i++) a[i] = Qs[((ty << 2) + i) * 65 + kk];
#pragma unroll
            for (int j = 0; j < 2; j++) bq[j] = Ks[((tx << 1) + j) * 65 + kk];
#pragma unroll
            for (int i = 0; i < 4; i++)
#pragma unroll
                for (int j = 0; j < 2; j++) accS[i][j] += a[i] * bq[j];
        }
        int krem = n - (kt << 5);
#pragma unroll
        for (int i = 0; i < 4; i++)
#pragma unroll
            for (int j = 0; j < 2; j++) {
                int col = (tx << 1) + j;
                Ss[((ty << 2) + i) * 33 + col] =
                    (col < krem) ? accS[i][j] * 0.125f : -1e30f;
            }
        __syncthreads();
        if (tid < 64) {
            float mold = ms[tid];
            float mx = mold;
            float* srow = Ss + tid * 33;
#pragma unroll 8
            for (int k2 = 0; k2 < 32; k2++) mx = fmaxf(mx, srow[k2]);
            float sc = __expf(mold - mx);
            float lsum = ls[tid] * sc;
#pragma unroll 8
            for (int k2 = 0; k2 < 32; k2++) {
                float p = __expf(srow[k2] - mx);
                srow[k2] = p;
                lsum += p;
            }
            ms[tid] = mx; ls[tid] = lsum; rs[tid] = sc;
        }
        __syncthreads();
#pragma unroll
        for (int i = 0; i < 4; i++) {
            float f = rs[(ty << 2) + i];
#pragma unroll
            for (int j = 0; j < 4; j++) accO[i][j] *= f;
        }
#pragma unroll 8
        for (int kk = 0; kk < 32; kk++) {
            float p[4], vv[4];
#pragma unroll
            for (int i = 0; i < 4; i++) p[i] = Ss[((ty << 2) + i) * 33 + kk];
#pragma unroll
            for (int j = 0; j < 4; j++) vv[j] = Vs[kk * 65 + (tx << 2) + j];
#pragma unroll
            for (int i = 0; i < 4; i++)
#pragma unroll
                for (int j = 0; j < 4; j++) accO[i][j] += p[i] * vv[j];
        }
    }
    __syncthreads();
    if (tid < 64) {
        float m = ms[tid];
        float M = fmaxf(m, 0.f);
        float denom = ls[tid] * __expf(m - M) + (float)(Tt - n) * __expf(-M);
        rs[tid] = __expf(m - M) / denom;
    }
    __syncthreads();
#pragma unroll
    for (int i = 0; i < 4; i++) {
        int r = (ty << 2) + i;
        int tok = qtk[r];
        if (tok < 0) continue;
        float f = rs[r];
        float4 o;
        o.x = accO[i][0] * f; o.y = accO[i][1] * f;
        o.z = accO[i][2] * f; o.w = accO[i][3] * f;
        *(float4*)(g_ctx + (size_t)(b * Tt + tok) * Dd + (h << 6) + (tx << 2)) = o;
    }
}

// ---------------- launch ---------------------------------------------------
extern "C" void kernel_launch(void* const* d_in, const int* in_sizes, int n_in,
                              void* d_out, int out_size) {
    const float* X    = (const float*)d_in[0];
    const float* Wc   = (const float*)d_in[1];
    const float* bc   = (const float*)d_in[2];
    const float* Win  = (const float*)d_in[3];
    const float* bin  = (const float*)d_in[4];
    const float* Wout = (const float*)d_in[5];
    const float* bout = (const float*)d_in[6];
    float* out = (float*)d_out;

    k_assign<<<(Bc * Tt) / 8, 256>>>(X, Wc, bc);
    k_rank<<<Bc, 1024>>>();
    k_split<0><<<2048, 256>>>((const float4*)X, Bc * Tt * Dd / 4);
    k_split<1><<<768, 256>>>((const float4*)Win, 3 * Dd * Dd / 4);
    k_split<2><<<256, 256>>>((const float4*)Wout, Dd * Dd / 4);
    k_gemm_mma<0><<<dim3(12, 32), 256>>>(bin, nullptr);
    k_attn<<<Bc * Cc * Hh * 16, 256>>>();
    k_split<3><<<2048, 256>>>(nullptr, Bc * Tt * Dd / 4);
    k_gemm_mma<1><<<dim3(4, 32), 256>>>(bout, out);
}

// round 4
// speedup vs baseline: 3.2680x; 2.2452x over previous
#include <cuda_runtime.h>
#include <cuda_bf16.h>
#include <cstdint>

#define Bc 4
#define Tt 1024
#define Dd 512
#define Cc 8
#define Hh 8

// ---------------- scratch (device globals) ---------------------------------
__device__ float g_ctx[Bc * Tt * Dd];
__device__ int   g_assign[Bc * Tt];
__device__ int   g_counts[Bc * Cc];
__device__ int   g_list[Bc * Tt];
// Q/K/V bf16 hi/lo planes, layout [B,H,T,64]
#define PLN (Bc * Hh * Tt * 64)
__device__ __nv_bfloat16 g_Qhi[PLN], g_Qlo[PLN];
__device__ __nv_bfloat16 g_Khi[PLN], g_Klo[PLN];
__device__ __nv_bfloat16 g_Vhi[PLN], g_Vlo[PLN];

static __device__ __forceinline__ uint32_t s2u(const void* p) {
    uint32_t a;
    asm("{ .reg .u64 t; cvta.to.shared.u64 t, %1; cvt.u32.u64 %0, t; }" : "=r"(a) : "l"(p));
    return a;
}
#define LDSM4(r0, r1, r2, r3, addr) \
    asm volatile("ldmatrix.sync.aligned.m8n8.x4.shared.b16 {%0,%1,%2,%3}, [%4];" \
                 : "=r"(r0), "=r"(r1), "=r"(r2), "=r"(r3) : "r"(addr))
#define LDSM4T(r0, r1, r2, r3, addr) \
    asm volatile("ldmatrix.sync.aligned.m8n8.x4.trans.shared.b16 {%0,%1,%2,%3}, [%4];" \
                 : "=r"(r0), "=r"(r1), "=r"(r2), "=r"(r3) : "r"(addr))
#define MMA16816(d, a, b0, b1) \
    asm volatile("mma.sync.aligned.m16n8k16.row.col.f32.bf16.bf16.f32 " \
                 "{%0,%1,%2,%3}, {%4,%5,%6,%7}, {%8,%9}, {%0,%1,%2,%3};" \
                 : "+f"((d)[0]), "+f"((d)[1]), "+f"((d)[2]), "+f"((d)[3]) \
                 : "r"((a)[0]), "r"((a)[1]), "r"((a)[2]), "r"((a)[3]), \
                   "r"((b0)), "r"((b1)))

static __device__ __forceinline__ uint32_t packbf(float x, float y) {
    __nv_bfloat162 t = __halves2bfloat162(__float2bfloat16(x), __float2bfloat16(y));
    return *(uint32_t*)&t;
}

// ---------------- 1) cluster argmax (fp32 Kahan, x cached in regs) --------
__global__ void k_assign(const float* __restrict__ X,
                         const float* __restrict__ Wc,
                         const float* __restrict__ bc) {
    int gw   = (blockIdx.x * blockDim.x + threadIdx.x) >> 5;
    int lane = threadIdx.x & 31;
    if (gw >= Bc * Tt) return;
    const float4* x4 = (const float4*)(X + (size_t)gw * Dd);
    float4 xr[4];
#pragma unroll
    for (int r = 0; r < 4; r++) xr[r] = x4[lane + (r << 5)];
    float best = -1e30f; int bi = 0;
#pragma unroll
    for (int c = 0; c < Cc; c++) {
        const float4* w4 = (const float4*)(Wc + c * Dd);
        float sum = 0.f, comp = 0.f;
#pragma unroll
        for (int r = 0; r < 4; r++) {
            float4 w = w4[lane + (r << 5)];
            float pr[4] = {xr[r].x * w.x, xr[r].y * w.y, xr[r].z * w.z, xr[r].w * w.w};
#pragma unroll
            for (int q = 0; q < 4; q++) {
                float y = pr[q] - comp;
                float t = sum + y;
                comp = (t - sum) - y;
                sum = t;
            }
        }
#pragma unroll
        for (int o = 16; o; o >>= 1) sum += __shfl_xor_sync(0xffffffffu, sum, o);
        float s = sum + bc[c];
        if (s > best) { best = s; bi = c; }
    }
    if (lane == 0) g_assign[gw] = bi;
}

// ---------------- 2) stable per-cluster rank via ballots -------------------
__global__ void __launch_bounds__(1024) k_rank() {
    __shared__ int warp_hist[32][8];
    __shared__ int tot[8];
    int b = blockIdx.x, t = threadIdx.x;
    int c = g_assign[b * Tt + t];
    int lane = t & 31, w = t >> 5;
    int rank_in_warp = 0;
#pragma unroll
    for (int cc = 0; cc < 8; cc++) {
        unsigned m = __ballot_sync(0xffffffffu, c == cc);
        if (cc == c) rank_in_warp = __popc(m & ((1u << lane) - 1u));
        if (lane == 0) warp_hist[w][cc] = __popc(m);
    }
    __syncthreads();
    if (t < 8) {
        int s = 0;
        for (int ww = 0; ww < 32; ww++) s += warp_hist[ww][t];
        tot[t] = s;
        g_counts[b * Cc + t] = s;
    }
    __syncthreads();
    int before = 0;
    for (int ww = 0; ww < w; ww++) before += warp_hist[ww][c];
    int base = 0;
    for (int i = 0; i < c; i++) base += tot[i];
    g_list[b * Tt + base + before + rank_in_warp] = t;
}

// ---------------- 3/5) HMMA split GEMM, fused fp32->bf16, reg prefetch ----
// C[M,N] = A[M,512]*B[N,512]^T + bias (3-term hi/lo split).
// MODE 0: A=X, B=Win -> bf16 hi/lo planes of Q/K/V. MODE 1: A=g_ctx, B=Wout -> Co.
#define APAD 40
template <int MODE>
__global__ void __launch_bounds__(256) k_gemm_mma(
    const float* __restrict__ Asrc, const float* __restrict__ Bsrc,
    const float* __restrict__ bias, float* __restrict__ Co) {
    __shared__ __nv_bfloat16 sA[2][128][APAD];
    __shared__ __nv_bfloat16 sB[2][128][APAD];
    const float* A = (MODE == 1) ? g_ctx : Asrc;

    const int tid = threadIdx.x;
    const int lane = tid & 31, wid = tid >> 5;
    const int bm = blockIdx.y << 7, bn = blockIdx.x << 7;
    const int wm = (wid >> 2) << 6;
    const int wn = (wid & 3) << 5;

    const uint32_t sbA = s2u(&sA[0][0][0]);
    const uint32_t sbB = s2u(&sB[0][0][0]);
    const int mq = lane >> 3, ri = lane & 7;
    const uint32_t aBase = sbA + (uint32_t)((wm + ((mq & 1) << 3) + ri) * (APAD * 2) + ((mq >> 1) << 4));
    const uint32_t bBase = sbB + (uint32_t)((wn + ((mq >> 1) << 3) + ri) * (APAD * 2) + ((mq & 1) << 4));
    const uint32_t HOFF = 128 * APAD * 2;

    float acc[4][4][4];
#pragma unroll
    for (int i = 0; i < 4; i++)
#pragma unroll
        for (int j = 0; j < 4; j++)
#pragma unroll
            for (int q = 0; q < 4; q++) acc[i][j][q] = 0.f;

    uint4 pa[4], pb[4];
#pragma unroll
    for (int r = 0; r < 4; r++) {
        int f = tid + (r << 8);
        int row = f >> 3, seg = f & 7;
        pa[r] = *(const uint4*)(A    + (size_t)(bm + row) * 512 + (seg << 2));
        pb[r] = *(const uint4*)(Bsrc + (size_t)(bn + row) * 512 + (seg << 2));
    }

    for (int kc = 0; kc < 16; kc++) {
        // convert prefetched fp32 -> hi/lo bf16 and store to smem
#pragma unroll
        for (int r = 0; r < 4; r++) {
            int f = tid + (r << 8);
            int row = f >> 3, seg = f & 7;
            float4 va = *(float4*)&pa[r];
            float4 vb = *(float4*)&pb[r];
            uint32_t ah0 = packbf(va.x, va.y), ah1 = packbf(va.z, va.w);
            __nv_bfloat162 h01 = *(__nv_bfloat162*)&ah0;
            __nv_bfloat162 h23 = *(__nv_bfloat162*)&ah1;
            uint32_t al0 = packbf(va.x - __bfloat162float(h01.x), va.y - __bfloat162float(h01.y));
            uint32_t al1 = packbf(va.z - __bfloat162float(h23.x), va.w - __bfloat162float(h23.y));
            *(uint32_t*)&sA[0][row][seg << 2]       = ah0;
            *(uint32_t*)&sA[0][row][(seg << 2) + 2] = ah1;
            *(uint32_t*)&sA[1][row][seg << 2]       = al0;
            *(uint32_t*)&sA[1][row][(seg << 2) + 2] = al1;
            uint32_t bh0 = packbf(vb.x, vb.y), bh1 = packbf(vb.z, vb.w);
            __nv_bfloat162 g01 = *(__nv_bfloat162*)&bh0;
            __nv_bfloat162 g23 = *(__nv_bfloat162*)&bh1;
            uint32_t bl0 = packbf(vb.x - __bfloat162float(g01.x), vb.y - __bfloat162float(g01.y));
            uint32_t bl1 = packbf(vb.z - __bfloat162float(g23.x), vb.w - __bfloat162float(g23.y));
            *(uint32_t*)&sB[0][row][seg << 2]       = bh0;
            *(uint32_t*)&sB[0][row][(seg << 2) + 2] = bh1;
            *(uint32_t*)&sB[1][row][seg << 2]       = bl0;
            *(uint32_t*)&sB[1][row][(seg << 2) + 2] = bl1;
        }
        __syncthreads();
        if (kc < 15) {
#pragma unroll
            for (int r = 0; r < 4; r++) {
                int f = tid + (r << 8);
                int row = f >> 3, seg = f & 7;
                pa[r] = *(const uint4*)(A    + (size_t)(bm + row) * 512 + (kc + 1) * 32 + (seg << 2));
                pb[r] = *(const uint4*)(Bsrc + (size_t)(bn + row) * 512 + (kc + 1) * 32 + (seg << 2));
            }
        }
#pragma unroll
        for (int k16 = 0; k16 < 2; k16++) {
            uint32_t ah[4][4], al[4][4], bh[4][2], bl[4][2];
#pragma unroll
            for (int i = 0; i < 4; i++) {
                uint32_t ad = aBase + i * (16 * APAD * 2) + k16 * 32;
                LDSM4(ah[i][0], ah[i][1], ah[i][2], ah[i][3], ad);
                LDSM4(al[i][0], al[i][1], al[i][2], al[i][3], ad + HOFF);
            }
#pragma unroll
            for (int j2 = 0; j2 < 2; j2++) {
                uint32_t bd = bBase + j2 * (16 * APAD * 2) + k16 * 32;
                LDSM4(bh[j2 * 2][0], bh[j2 * 2][1], bh[j2 * 2 + 1][0], bh[j2 * 2 + 1][1], bd);
                LDSM4(bl[j2 * 2][0], bl[j2 * 2][1], bl[j2 * 2 + 1][0], bl[j2 * 2 + 1][1], bd + HOFF);
            }
#pragma unroll
            for (int i = 0; i < 4; i++)
#pragma unroll
                for (int j = 0; j < 4; j++) {
                    MMA16816(acc[i][j], ah[i], bh[j][0], bh[j][1]);
                    MMA16816(acc[i][j], ah[i], bl[j][0], bl[j][1]);
                    MMA16816(acc[i][j], al[i], bh[j][0], bh[j][1]);
                }
        }
        __syncthreads();
    }

    const int g = lane >> 2, q4 = lane & 3;
#pragma unroll
    for (int i = 0; i < 4; i++)
#pragma unroll
        for (int j = 0; j < 4; j++)
#pragma unroll
            for (int p = 0; p < 2; p++) {
                int m = bm + wm + i * 16 + g + p * 8;
                int n = bn + wn + j * 8 + q4 * 2;
                float2 v;
                v.x = acc[i][j][p * 2 + 0] + bias[n + 0];
                v.y = acc[i][j][p * 2 + 1] + bias[n + 1];
                if (MODE == 0) {
                    int part = n >> 9, nn = n & 511, h = nn >> 6, d = nn & 63;
                    int b_ = m >> 10, t = m & 1023;
                    size_t idx = (((size_t)(b_ * Hh + h) * Tt + t) << 6) + d;
                    uint32_t hv = packbf(v.x, v.y);
                    __nv_bfloat162 h2 = *(__nv_bfloat162*)&hv;
                    uint32_t lv = packbf(v.x - __bfloat162float(h2.x),
                                         v.y - __bfloat162float(h2.y));
                    __nv_bfloat16 *ph, *pl;
                    if (part == 0)      { ph = g_Qhi; pl = g_Qlo; }
                    else if (part == 1) { ph = g_Khi; pl = g_Klo; }
                    else                { ph = g_Vhi; pl = g_Vlo; }
                    *(uint32_t*)(ph + idx) = hv;
                    *(uint32_t*)(pl + idx) = lv;
                } else {
                    *(float2*)(Co + (size_t)m * 512 + n) = v;
                }
            }
}

// ---------------- 4) HMMA cluster-gathered flash attention ----------------
// block = (b, cluster, head, q-tile 64). 4 warps; warp handles 16 q-rows.
// S = QK^T (3-term hi/lo), online softmax in regs, O += P V (3-term hi/lo).
#define QPAD 72
__global__ void __launch_bounds__(128) k_attn() {
    __shared__ __nv_bfloat16 sQ[2][64][QPAD];
    __shared__ __nv_bfloat16 sK[2][32][QPAD];
    __shared__ __nv_bfloat16 sV[2][32][QPAD];
    __shared__ int qtk[64], ktk[32];

    int bid = blockIdx.x;
    int qt = bid & 15, h = (bid >> 4) & 7, c = (bid >> 7) & 7, b = bid >> 10;
    int n = g_counts[b * Cc + c];
    if (qt * 64 >= n) return;
    int base = 0;
#pragma unroll
    for (int i = 0; i < Cc; i++) base += (i < c) ? g_counts[b * Cc + i] : 0;

    int tid = threadIdx.x, lane = tid & 31, wid = tid >> 5;
    if (tid < 64) {
        int qi = qt * 64 + tid;
        qtk[tid] = (qi < n) ? g_list[b * Tt + base + qi] : -1;
    }
    __syncthreads();

    const size_t hb = ((size_t)(b * Hh + h)) << 16;   // (b,h) plane base, T*64
    const uint4 z4 = make_uint4(0, 0, 0, 0);
    // load Q hi/lo planes (gathered)
#pragma unroll
    for (int r = 0; r < 8; r++) {
        int f = tid + (r << 7);
        int pl = f >> 9, rem = f & 511, row = rem >> 3, seg = rem & 7;
        int tok = qtk[row];
        const __nv_bfloat16* src = pl ? g_Qlo : g_Qhi;
        uint4 v = (tok >= 0) ? *(const uint4*)(src + hb + ((size_t)tok << 6) + (seg << 3)) : z4;
        *(uint4*)&sQ[pl][row][seg << 3] = v;
    }
    __syncthreads();

    const int mq = lane >> 3, ri = lane & 7;
    const uint32_t QPLANE = 64 * QPAD * 2;
    const uint32_t KPLANE = 32 * QPAD * 2;
    uint32_t qb = s2u(&sQ[0][0][0]) +
                  (uint32_t)((wid * 16 + ((mq & 1) << 3) + ri) * (QPAD * 2) + ((mq >> 1) << 4));
    uint32_t qh[4][4], ql[4][4];
#pragma unroll
    for (int s = 0; s < 4; s++) {
        LDSM4(qh[s][0], qh[s][1], qh[s][2], qh[s][3], qb + s * 32);
        LDSM4(ql[s][0], ql[s][1], ql[s][2], ql[s][3], qb + QPLANE + s * 32);
    }

    uint32_t kb = s2u(&sK[0][0][0]) +
                  (uint32_t)((((mq >> 1) << 3) + ri) * (QPAD * 2) + ((mq & 1) << 4));
    uint32_t vb = s2u(&sV[0][0][0]) +
                  (uint32_t)(((((lane >> 3) & 1) << 3) + ri) * (QPAD * 2) + ((lane >> 4) << 4));

    float accO[8][4];
#pragma unroll
    for (int jo = 0; jo < 8; jo++)
#pragma unroll
        for (int q = 0; q < 4; q++) accO[jo][q] = 0.f;
    float m2[2] = {-1e30f, -1e30f}, l2[2] = {0.f, 0.f};

    int nkt = (n + 31) >> 5;
    for (int kt = 0; kt < nkt; kt++) {
        __syncthreads();
        if (tid < 32) {
            int ki = (kt << 5) + tid;
            ktk[tid] = (ki < n) ? g_list[b * Tt + base + ki] : -1;
        }
        __syncthreads();
#pragma unroll
        for (int r = 0; r < 8; r++) {
            int f = tid + (r << 7);
            int pl = f >> 8, rem = f & 255, row = rem >> 3, seg = rem & 7;
            int tok = ktk[row];
            const __nv_bfloat16* src = (pl == 0) ? g_Khi : (pl == 1) ? g_Klo
                                     : (pl == 2) ? g_Vhi : g_Vlo;
            uint4 v = (tok >= 0) ? *(const uint4*)(src + hb + ((size_t)tok << 6) + (seg << 3)) : z4;
            void* dst = (pl < 2) ? (void*)&sK[pl][row][seg << 3] : (void*)&sV[pl - 2][row][seg << 3];
            *(uint4*)dst = v;
        }
        __syncthreads();

        // ---- S = Q K^T (3-term) ----
        float sf[4][4];
#pragma unroll
        for (int j = 0; j < 4; j++)
#pragma unroll
            for (int q = 0; q < 4; q++) sf[j][q] = 0.f;
#pragma unroll
        for (int s = 0; s < 4; s++) {
            uint32_t bh[4][2], bl[4][2];
#pragma unroll
            for (int np = 0; np < 2; np++) {
                uint32_t ad = kb + np * (16 * QPAD * 2) + s * 32;
                LDSM4(bh[np * 2][0], bh[np * 2][1], bh[np * 2 + 1][0], bh[np * 2 + 1][1], ad);
                LDSM4(bl[np * 2][0], bl[np * 2][1], bl[np * 2 + 1][0], bl[np * 2 + 1][1], ad + KPLANE);
            }
#pragma unroll
            for (int j = 0; j < 4; j++) {
                MMA16816(sf[j], qh[s], bh[j][0], bh[j][1]);
                MMA16816(sf[j], qh[s], bl[j][0], bl[j][1]);
                MMA16816(sf[j], ql[s], bh[j][0], bh[j][1]);
            }
        }
        int krem = n - (kt << 5);
#pragma unroll
        for (int j = 0; j < 4; j++)
#pragma unroll
            for (int q = 0; q < 4; q++) {
                int col = (j << 3) + ((lane & 3) << 1) + (q & 1);
                sf[j][q] = (col < krem) ? sf[j][q] * 0.125f : -1e30f;
            }
        // ---- online softmax (rows g and g+8) ----
        float mx0 = -1e30f, mx1 = -1e30f;
#pragma unroll
        for (int j = 0; j < 4; j++) {
            mx0 = fmaxf(mx0, fmaxf(sf[j][0], sf[j][1]));
            mx1 = fmaxf(mx1, fmaxf(sf[j][2], sf[j][3]));
        }
        mx0 = fmaxf(mx0, __shfl_xor_sync(0xffffffffu, mx0, 1));
        mx0 = fmaxf(mx0, __shfl_xor_sync(0xffffffffu, mx0, 2));
        mx1 = fmaxf(mx1, __shfl_xor_sync(0xffffffffu, mx1, 1));
        mx1 = fmaxf(mx1, __shfl_xor_sync(0xffffffffu, mx1, 2));
        float mn0 = fmaxf(m2[0], mx0), mn1 = fmaxf(m2[1], mx1);
        float r0 = __expf(m2[0] - mn0), r1 = __expf(m2[1] - mn1);
        float rs0 = 0.f, rs1 = 0.f;
#pragma unroll
        for (int j = 0; j < 4; j++) {
            sf[j][0] = __expf(sf[j][0] - mn0); rs0 += sf[j][0];
            sf[j][1] = __expf(sf[j][1] - mn0); rs0 += sf[j][1];
            sf[j][2] = __expf(sf[j][2] - mn1); rs1 += sf[j][2];
            sf[j][3] = __expf(sf[j][3] - mn1); rs1 += sf[j][3];
        }
        rs0 += __shfl_xor_sync(0xffffffffu, rs0, 1);
        rs0 += __shfl_xor_sync(0xffffffffu, rs0, 2);
        rs1 += __shfl_xor_sync(0xffffffffu, rs1, 1);
        rs1 += __shfl_xor_sync(0xffffffffu, rs1, 2);
        l2[0] = l2[0] * r0 + rs0;
        l2[1] = l2[1] * r1 + rs1;
        m2[0] = mn0; m2[1] = mn1;
#pragma unroll
        for (int jo = 0; jo < 8; jo++) {
            accO[jo][0] *= r0; accO[jo][1] *= r0;
            accO[jo][2] *= r1; accO[jo][3] *= r1;
        }
        // ---- pack P hi/lo as A fragments (k16 step s2 over 32 keys) ----
        uint32_t ph[2][4], plo[2][4];
#pragma unroll
        for (int s2 = 0; s2 < 2; s2++) {
            float c0a = sf[2 * s2][0],     c1a = sf[2 * s2][1];
            float c2a = sf[2 * s2][2],     c3a = sf[2 * s2][3];
            float c0b = sf[2 * s2 + 1][0], c1b = sf[2 * s2 + 1][1];
            float c2b = sf[2 * s2 + 1][2], c3b = sf[2 * s2 + 1][3];
            ph[s2][0] = packbf(c0a, c1a); ph[s2][1] = packbf(c2a, c3a);
            ph[s2][2] = packbf(c0b, c1b); ph[s2][3] = packbf(c2b, c3b);
            __nv_bfloat162 t0 = *(__nv_bfloat162*)&ph[s2][0];
            __nv_bfloat162 t1 = *(__nv_bfloat162*)&ph[s2][1];
            __nv_bfloat162 t2 = *(__nv_bfloat162*)&ph[s2][2];
            __nv_bfloat162 t3 = *(__nv_bfloat162*)&ph[s2][3];
            plo[s2][0] = packbf(c0a - __bfloat162float(t0.x), c1a - __bfloat162float(t0.y));
            plo[s2][1] = packbf(c2a - __bfloat162float(t1.x), c3a - __bfloat162float(t1.y));
            plo[s2][2] = packbf(c0b - __bfloat162float(t2.x), c1b - __bfloat162float(t2.y));
            plo[s2][3] = packbf(c2b - __bfloat162float(t3.x), c3b - __bfloat162float(t3.y));
        }
        // ---- O += P V (3-term; V via ldmatrix.trans) ----
#pragma unroll
        for (int s2 = 0; s2 < 2; s2++) {
#pragma unroll
            for (int jp = 0; jp < 4; jp++) {
                uint32_t vh0, vh1, vh2, vh3, vl0, vl1, vl2, vl3;
                uint32_t ad = vb + s2 * (16 * QPAD * 2) + jp * 32;
                LDSM4T(vh0, vh1, vh2, vh3, ad);
                LDSM4T(vl0, vl1, vl2, vl3, ad + KPLANE);
                MMA16816(accO[2 * jp],     ph[s2],  vh0, vh1);
                MMA16816(accO[2 * jp],     ph[s2],  vl0, vl1);
                MMA16816(accO[2 * jp],     plo[s2], vh0, vh1);
                MMA16816(accO[2 * jp + 1], ph[s2],  vh2, vh3);
                MMA16816(accO[2 * jp + 1], ph[s2],  vl2, vl3);
                MMA16816(accO[2 * jp + 1], plo[s2], vh2, vh3);
            }
        }
    }
    // ---- fold (T-n) zero-keys into denominator; write out ----
    float M0 = fmaxf(m2[0], 0.f), M1 = fmaxf(m2[1], 0.f);
    float e0 = __expf(m2[0] - M0), e1 = __expf(m2[1] - M1);
    float f0 = e0 / (l2[0] * e0 + (float)(Tt - n) * __expf(-M0));
    float f1 = e1 / (l2[1] * e1 + (float)(Tt - n) * __expf(-M1));
    int g = lane >> 2;
    int row0 = wid * 16 + g, row1 = row0 + 8;
    int t0 = qtk[row0], t1 = qtk[row1];
#pragma unroll
    for (int jo = 0; jo < 8; jo++) {
        int col = (jo << 3) + ((lane & 3) << 1);
        if (t0 >= 0) {
            float2 v = {accO[jo][0] * f0, accO[jo][1] * f0};
            *(float2*)(g_ctx + ((size_t)(b * Tt + t0)) * Dd + (h << 6) + col) = v;
        }
        if (t1 >= 0) {
            float2 v = {accO[jo][2] * f1, accO[jo][3] * f1};
            *(float2*)(g_ctx + ((size_t)(b * Tt + t1)) * Dd + (h << 6) + col) = v;
        }
    }
}

// ---------------- launch ---------------------------------------------------
extern "C" void kernel_launch(void* const* d_in, const int* in_sizes, int n_in,
                              void* d_out, int out_size) {
    const float* X    = (const float*)d_in[0];
    const float* Wc   = (const float*)d_in[1];
    const float* bc   = (const float*)d_in[2];
    const float* Win  = (const float*)d_in[3];
    const float* bin  = (const float*)d_in[4];
    const float* Wout = (const float*)d_in[5];
    const float* bout = (const float*)d_in[6];
    float* out = (float*)d_out;

    k_assign<<<(Bc * Tt) / 8, 256>>>(X, Wc, bc);
    k_rank<<<Bc, 1024>>>();
    k_gemm_mma<0><<<dim3(12, 32), 256>>>(X, Win, bin, nullptr);
    k_attn<<<Bc * Cc * Hh * 16, 128>>>();
    k_gemm_mma<1><<<dim3(4, 32), 256>>>(nullptr, Wout, bout, out);
}